// round 4
// baseline (speedup 1.0000x reference)
#include <cuda_runtime.h>
#include <math.h>

// ---------------- problem constants ----------------
#define N_TOK 4096     // B*S
#define CDIM  768      // C = nh*Dh
#define NCLU  32
#define SDIM  1024
// v_ext: [48][24][24][64]

// ---------------- scratch (static device memory; no allocs allowed) --------
__device__ float g_csum[NCLU * CDIM];                 // cluster feature sums
__device__ float g_qn[N_TOK * CDIM];                  // l2norm(proxy)
__device__ float g_kn[N_TOK * CDIM];                  // l2norm(x)
__device__ float g_v2[N_TOK * CDIM];                  // resized V, [n][h*64+d]
__device__ float g_sim[(size_t)N_TOK * N_TOK];        // similarity / softmax probs

// ---------------- packed f32x2 helpers ----------------
__device__ __forceinline__ unsigned long long pk2(float x, float y) {
    unsigned long long r;
    asm("mov.b64 %0, {%1, %2};" : "=l"(r) : "f"(x), "f"(y));
    return r;
}
__device__ __forceinline__ void upk2(unsigned long long v, float& x, float& y) {
    asm("mov.b64 {%0, %1}, %2;" : "=f"(x), "=f"(y) : "l"(v));
}
__device__ __forceinline__ unsigned long long ffma2(unsigned long long a,
                                                    unsigned long long b,
                                                    unsigned long long c) {
    unsigned long long d;
    asm("fma.rn.f32x2 %0, %1, %2, %3;" : "=l"(d) : "l"(a), "l"(b), "l"(c));
    return d;
}

// ---------------- kernel 0: zero cluster sums ----------------
__global__ void k_zero() {
    int t = blockIdx.x * 256 + threadIdx.x;
    if (t < NCLU * CDIM) g_csum[t] = 0.f;
}

// ---------------- kernel 1: bilinear resize 24x24 -> 32x32 ----------------
// V2[n][h*64+d] = bilerp(v_ext[b*12+h][:, :, d]) at (y, x), half-pixel centers,
// edge clamp (matches jax.image.resize 'bilinear' upsample).
__global__ void k_resize(const float* __restrict__ vext) {
    int col = blockIdx.y * 256 + threadIdx.x;   // 0..767
    int n = blockIdx.x;                          // 0..4095
    int h = col >> 6, d = col & 63;
    int b = n >> 10, s = n & 1023, yy = s >> 5, xx = s & 31;

    float sy = 0.75f * (float)yy - 0.125f;
    float sx = 0.75f * (float)xx - 0.125f;
    float fy0 = floorf(sy), fx0 = floorf(sx);
    int y0 = (int)fy0, x0 = (int)fx0;
    float fy = sy - fy0, fx = sx - fx0;
    int y0c = max(y0, 0), y1c = min(y0 + 1, 23);
    int x0c = max(x0, 0), x1c = min(x0 + 1, 23);

    const float* base = vext + ((size_t)(b * 12 + h)) * (24 * 24 * 64) + d;
    float v00 = base[(y0c * 24 + x0c) * 64];
    float v01 = base[(y0c * 24 + x1c) * 64];
    float v10 = base[(y1c * 24 + x0c) * 64];
    float v11 = base[(y1c * 24 + x1c) * 64];
    float top = v00 + fx * (v01 - v00);
    float bot = v10 + fx * (v11 - v10);
    g_v2[n * CDIM + col] = top + fy * (bot - top);
}

// ---------------- kernel 2: per-cluster feature sums ----------------
__global__ void k_csum(const float* __restrict__ x, const int* __restrict__ idx) {
    int t = blockIdx.x * 256 + threadIdx.x;     // 0 .. 4096*768-1
    int row = t / CDIM;
    int col = t - row * CDIM;
    int cl = __ldg(&idx[row]);
    atomicAdd(&g_csum[cl * CDIM + col], x[t]);
}

// ---------------- kernel 3: proxy + normalization ----------------
// proxy_i  = csum[label_i] + sum of (<=8) same-block neighbors with different label
// (count division dropped: l2norm is scale-invariant, count > 0 always)
__global__ __launch_bounds__(256) void k_proxy(const float* __restrict__ x,
                                               const int* __restrict__ idx) {
    __shared__ float red[256];
    int i = blockIdx.x, t = threadIdx.x;
    int ci = __ldg(&idx[i]);
    int b = i >> 10, s = i & 1023, r = s >> 5, c = s & 31;

    int nb[8];
    int nnb = 0;
#pragma unroll
    for (int dr = -1; dr <= 1; dr++) {
#pragma unroll
        for (int dc = -1; dc <= 1; dc++) {
            if (dr == 0 && dc == 0) continue;
            int rr = r + dr, cc = c + dc;
            if (rr >= 0 && rr < 32 && cc >= 0 && cc < 32) {
                int j = (b << 10) + (rr << 5) + cc;
                if (__ldg(&idx[j]) != ci) nb[nnb++] = j;
            }
        }
    }

    float p[3], xi[3];
#pragma unroll
    for (int u = 0; u < 3; u++) {
        int col = t + u * 256;
        float v = g_csum[ci * CDIM + col];
        for (int q = 0; q < nnb; q++) v += x[nb[q] * CDIM + col];
        p[u] = v;
        xi[u] = x[i * CDIM + col];
    }

    float ssp = p[0] * p[0] + p[1] * p[1] + p[2] * p[2];
    float ssx = xi[0] * xi[0] + xi[1] * xi[1] + xi[2] * xi[2];

    red[t] = ssp; __syncthreads();
    for (int w = 128; w > 0; w >>= 1) { if (t < w) red[t] += red[t + w]; __syncthreads(); }
    float SSP = red[0]; __syncthreads();
    red[t] = ssx; __syncthreads();
    for (int w = 128; w > 0; w >>= 1) { if (t < w) red[t] += red[t + w]; __syncthreads(); }
    float SSX = red[0];

    float ip = 1.f / fmaxf(sqrtf(SSP), 1e-12f);
    float ix = 1.f / fmaxf(sqrtf(SSX), 1e-12f);
#pragma unroll
    for (int u = 0; u < 3; u++) {
        int col = t + u * 256;
        g_qn[i * CDIM + col] = p[u] * ip;
        g_kn[i * CDIM + col] = xi[u] * ix;
    }
}

// ---------------- shared GEMM micro-kernel (128x128 tile, 8x8/thread, f32x2) --
__device__ __forceinline__ void mma16(const float (*__restrict__ As)[132],
                                      const float (*__restrict__ Bs)[132],
                                      int ty8, int tx8,
                                      unsigned long long acc[8][4]) {
#pragma unroll
    for (int k = 0; k < 16; k++) {
        float4 a0 = *(const float4*)&As[k][ty8];
        float4 a1 = *(const float4*)&As[k][ty8 + 4];
        float4 b0 = *(const float4*)&Bs[k][tx8];
        float4 b1 = *(const float4*)&Bs[k][tx8 + 4];
        unsigned long long bp0 = pk2(b0.x, b0.y);
        unsigned long long bp1 = pk2(b0.z, b0.w);
        unsigned long long bp2 = pk2(b1.x, b1.y);
        unsigned long long bp3 = pk2(b1.z, b1.w);
        float av[8] = {a0.x, a0.y, a0.z, a0.w, a1.x, a1.y, a1.z, a1.w};
#pragma unroll
        for (int i = 0; i < 8; i++) {
            unsigned long long ad = pk2(av[i], av[i]);
            acc[i][0] = ffma2(ad, bp0, acc[i][0]);
            acc[i][1] = ffma2(ad, bp1, acc[i][1]);
            acc[i][2] = ffma2(ad, bp2, acc[i][2]);
            acc[i][3] = ffma2(ad, bp3, acc[i][3]);
        }
    }
}

// ---------------- kernel 4: SIM = QN @ KN^T  (M=N=4096, K=768, both K-major) --
__global__ __launch_bounds__(256) void k_gemm1() {
    const int K = CDIM;
    __shared__ __align__(16) float As[2][16][132];
    __shared__ __align__(16) float Bs[2][16][132];
    int tid = threadIdx.x;
    int bx = blockIdx.x, by = blockIdx.y;
    const float* A = g_qn + by * 128 * K;
    const float* B = g_kn + bx * 128 * K;
    int lr = tid >> 2, lk = (tid & 3) << 2;
    int tx = tid & 15, ty = tid >> 4;
    int ty8 = ty * 8, tx8 = tx * 8;

    float4 pa0 = *(const float4*)(A + lr * K + lk);
    float4 pa1 = *(const float4*)(A + (lr + 64) * K + lk);
    float4 pb0 = *(const float4*)(B + lr * K + lk);
    float4 pb1 = *(const float4*)(B + (lr + 64) * K + lk);

    unsigned long long acc[8][4];
#pragma unroll
    for (int i = 0; i < 8; i++) { acc[i][0] = 0ULL; acc[i][1] = 0ULL; acc[i][2] = 0ULL; acc[i][3] = 0ULL; }

    const int NK = K / 16;
    int buf = 0;
#pragma unroll 1
    for (int kt = 0; kt < NK; kt++) {
        As[buf][lk + 0][lr] = pa0.x; As[buf][lk + 1][lr] = pa0.y;
        As[buf][lk + 2][lr] = pa0.z; As[buf][lk + 3][lr] = pa0.w;
        As[buf][lk + 0][lr + 64] = pa1.x; As[buf][lk + 1][lr + 64] = pa1.y;
        As[buf][lk + 2][lr + 64] = pa1.z; As[buf][lk + 3][lr + 64] = pa1.w;
        Bs[buf][lk + 0][lr] = pb0.x; Bs[buf][lk + 1][lr] = pb0.y;
        Bs[buf][lk + 2][lr] = pb0.z; Bs[buf][lk + 3][lr] = pb0.w;
        Bs[buf][lk + 0][lr + 64] = pb1.x; Bs[buf][lk + 1][lr + 64] = pb1.y;
        Bs[buf][lk + 2][lr + 64] = pb1.z; Bs[buf][lk + 3][lr + 64] = pb1.w;
        __syncthreads();
        if (kt + 1 < NK) {
            int k0 = (kt + 1) * 16;
            pa0 = *(const float4*)(A + lr * K + k0 + lk);
            pa1 = *(const float4*)(A + (lr + 64) * K + k0 + lk);
            pb0 = *(const float4*)(B + lr * K + k0 + lk);
            pb1 = *(const float4*)(B + (lr + 64) * K + k0 + lk);
        }
        mma16(As[buf], Bs[buf], ty8, tx8, acc);
        buf ^= 1;
    }

    int col0 = bx * 128 + tx8;
#pragma unroll
    for (int i = 0; i < 8; i++) {
        int row = by * 128 + ty8 + i;
        float4 v0, v1;
        upk2(acc[i][0], v0.x, v0.y); upk2(acc[i][1], v0.z, v0.w);
        upk2(acc[i][2], v1.x, v1.y); upk2(acc[i][3], v1.z, v1.w);
        float* Cp = g_sim + (size_t)row * N_TOK + col0;
        *(float4*)Cp = v0;
        *(float4*)(Cp + 4) = v1;
    }
}

// ---------------- kernel 5: row-wise token_norm + cut + softmax (in place) ---
__global__ __launch_bounds__(256) void k_softmax() {
    __shared__ __align__(16) float rowbuf[N_TOK];
    __shared__ float red[256];
    int row = blockIdx.x, t = threadIdx.x;
    float* Rp = g_sim + (size_t)row * N_TOK;

    float s = 0.f;
#pragma unroll
    for (int u = 0; u < 4; u++) {
        int c4 = t + u * 256;
        float4 v = ((const float4*)Rp)[c4];
        ((float4*)rowbuf)[c4] = v;
        s += (v.x + v.y) + (v.z + v.w);
    }
    red[t] = s; __syncthreads();
    for (int w = 128; w > 0; w >>= 1) { if (t < w) red[t] += red[t + w]; __syncthreads(); }
    float mean = fmaxf(red[0] * (1.f / 4096.f), 0.f);
    __syncthreads();

    float sub = mean * 1.2f;
    float mx = -3.402823466e38f;
#pragma unroll
    for (int u = 0; u < 4; u++) {
        int c4 = t + u * 256;
        float4 v = ((float4*)rowbuf)[c4];
        v.x = (v.x - sub) * 3.0f; v.y = (v.y - sub) * 3.0f;
        v.z = (v.z - sub) * 3.0f; v.w = (v.w - sub) * 3.0f;
        ((float4*)rowbuf)[c4] = v;
        mx = fmaxf(mx, fmaxf(fmaxf(v.x, v.y), fmaxf(v.z, v.w)));
    }
    red[t] = mx; __syncthreads();
    for (int w = 128; w > 0; w >>= 1) { if (t < w) red[t] = fmaxf(red[t], red[t + w]); __syncthreads(); }
    float M = red[0];
    __syncthreads();

    float cut = fminf(M, 0.1f);
    const float invT = 1.f / 0.07f;
    float zs = 0.f;
#pragma unroll
    for (int u = 0; u < 4; u++) {
        int c4 = t + u * 256;
        float4 v = ((float4*)rowbuf)[c4];
        v.x = (v.x < cut) ? 0.f : __expf((v.x - M) * invT);
        v.y = (v.y < cut) ? 0.f : __expf((v.y - M) * invT);
        v.z = (v.z < cut) ? 0.f : __expf((v.z - M) * invT);
        v.w = (v.w < cut) ? 0.f : __expf((v.w - M) * invT);
        ((float4*)rowbuf)[c4] = v;
        zs += (v.x + v.y) + (v.z + v.w);
    }
    red[t] = zs; __syncthreads();
    for (int w = 128; w > 0; w >>= 1) { if (t < w) red[t] += red[t + w]; __syncthreads(); }
    float inv = 1.f / red[0];

#pragma unroll
    for (int u = 0; u < 4; u++) {
        int c4 = t + u * 256;
        float4 v = ((float4*)rowbuf)[c4];
        v.x *= inv; v.y *= inv; v.z *= inv; v.w *= inv;
        ((float4*)Rp)[c4] = v;
    }
}

// ---------------- kernel 6: OUT = P @ V2 (M=4096, N=768, K=4096, NN) ---------
// epilogue scatters row (b*1024+s) -> out[s][b][:]
__global__ __launch_bounds__(256) void k_gemm2(float* __restrict__ out) {
    const int K = N_TOK;
    __shared__ __align__(16) float As[2][16][132];
    __shared__ __align__(16) float Bs[2][16][132];
    int tid = threadIdx.x;
    int bx = blockIdx.x, by = blockIdx.y;
    const float* A = g_sim + (size_t)by * 128 * K;
    const float* B = g_v2 + bx * 128;
    int lr = tid >> 2, lk = (tid & 3) << 2;
    int lkb = tid >> 4, lcb = (tid & 15) << 2;
    int tx = tid & 15, ty = tid >> 4;
    int ty8 = ty * 8, tx8 = tx * 8;

    float4 pa0 = *(const float4*)(A + lr * K + lk);
    float4 pa1 = *(const float4*)(A + (lr + 64) * K + lk);
    float4 pb0 = *(const float4*)(B + lkb * CDIM + lcb);
    float4 pb1 = *(const float4*)(B + lkb * CDIM + lcb + 64);

    unsigned long long acc[8][4];
#pragma unroll
    for (int i = 0; i < 8; i++) { acc[i][0] = 0ULL; acc[i][1] = 0ULL; acc[i][2] = 0ULL; acc[i][3] = 0ULL; }

    const int NK = K / 16;
    int buf = 0;
#pragma unroll 1
    for (int kt = 0; kt < NK; kt++) {
        As[buf][lk + 0][lr] = pa0.x; As[buf][lk + 1][lr] = pa0.y;
        As[buf][lk + 2][lr] = pa0.z; As[buf][lk + 3][lr] = pa0.w;
        As[buf][lk + 0][lr + 64] = pa1.x; As[buf][lk + 1][lr + 64] = pa1.y;
        As[buf][lk + 2][lr + 64] = pa1.z; As[buf][lk + 3][lr + 64] = pa1.w;
        *(float4*)&Bs[buf][lkb][lcb] = pb0;
        *(float4*)&Bs[buf][lkb][lcb + 64] = pb1;
        __syncthreads();
        if (kt + 1 < NK) {
            int k0 = (kt + 1) * 16;
            pa0 = *(const float4*)(A + lr * K + k0 + lk);
            pa1 = *(const float4*)(A + (lr + 64) * K + k0 + lk);
            pb0 = *(const float4*)(B + (k0 + lkb) * CDIM + lcb);
            pb1 = *(const float4*)(B + (k0 + lkb) * CDIM + lcb + 64);
        }
        mma16(As[buf], Bs[buf], ty8, tx8, acc);
        buf ^= 1;
    }

    int col0 = bx * 128 + tx8;
#pragma unroll
    for (int i = 0; i < 8; i++) {
        int row = by * 128 + ty8 + i;
        int orow = (row & 1023) * 4 + (row >> 10);   // s*B + b
        float4 v0, v1;
        upk2(acc[i][0], v0.x, v0.y); upk2(acc[i][1], v0.z, v0.w);
        upk2(acc[i][2], v1.x, v1.y); upk2(acc[i][3], v1.z, v1.w);
        float* Op = out + (size_t)orow * CDIM + col0;
        *(float4*)Op = v0;
        *(float4*)(Op + 4) = v1;
    }
}

// ---------------- launch ----------------
extern "C" void kernel_launch(void* const* d_in, const int* in_sizes, int n_in,
                              void* d_out, int out_size) {
    const float* ex = nullptr;
    const float* vext = nullptr;
    const int* idx = nullptr;
    for (int i = 0; i < n_in; i++) {
        if (in_sizes[i] == 4096) idx = (const int*)d_in[i];
        else if (in_sizes[i] == 2 * 2 * 1024 * 768) ex = (const float*)d_in[i];
        else if (in_sizes[i] == 48 * 24 * 24 * 64) vext = (const float*)d_in[i];
    }
    if (!ex || !vext || !idx) return;
    float* out = (float*)d_out;

    k_zero<<<96, 256>>>();
    k_resize<<<dim3(4096, 3), 256>>>(vext);
    k_csum<<<(N_TOK * CDIM) / 256, 256>>>(ex, idx);
    k_proxy<<<N_TOK, 256>>>(ex, idx);
    k_gemm1<<<dim3(32, 32), 256>>>();
    k_softmax<<<N_TOK, 256>>>();
    k_gemm2<<<dim3(6, 32), 256>>>(out);
}

// round 8
// speedup vs baseline: 1.8814x; 1.8814x over previous
#include <cuda_runtime.h>
#include <cuda_bf16.h>
#include <cstdint>
#include <math.h>

// ---------------- problem constants ----------------
#define N_TOK 4096     // B*S
#define CDIM  768      // C = nh*Dh
#define NCLU  32

// ---------------- scratch (static device memory; no allocs allowed) --------
__device__ __align__(256) float g_csum[NCLU * CDIM];
__device__ __align__(256) __nv_bfloat16 g_qnh[N_TOK * CDIM];   // l2norm(proxy) hi
__device__ __align__(256) __nv_bfloat16 g_qnl[N_TOK * CDIM];   // lo residual
__device__ __align__(256) __nv_bfloat16 g_knh[N_TOK * CDIM];   // l2norm(x) hi
__device__ __align__(256) __nv_bfloat16 g_knl[N_TOK * CDIM];
__device__ __align__(256) __nv_bfloat16 g_v2h[CDIM * N_TOK];   // resized V, TRANSPOSED [c][n]
__device__ __align__(256) __nv_bfloat16 g_v2l[CDIM * N_TOK];
__device__ __align__(256) float g_sim[(size_t)N_TOK * N_TOK];  // similarity (fp32)
__device__ __align__(256) __nv_bfloat16 g_ph[(size_t)N_TOK * N_TOK];  // probs hi
__device__ __align__(256) __nv_bfloat16 g_pl[(size_t)N_TOK * N_TOK];  // probs lo

// ---------------- PTX helpers (all baseline sm_80/75 features) -------------
__device__ __forceinline__ uint32_t smem_u32(const void* p) {
    uint32_t a;
    asm("{ .reg .u64 t; cvta.to.shared.u64 t, %1; cvt.u32.u64 %0, t; }" : "=r"(a) : "l"(p));
    return a;
}
#define CPA16(dst, src) \
    asm volatile("cp.async.cg.shared.global [%0], [%1], 16;" :: "r"(dst), "l"(src))
#define CP_COMMIT() asm volatile("cp.async.commit_group;")
#define CP_WAIT(n)  asm volatile("cp.async.wait_group %0;" :: "n"(n))

#define LDSM_X4(r0, r1, r2, r3, a) \
    asm volatile("ldmatrix.sync.aligned.m8n8.x4.shared.b16 {%0,%1,%2,%3}, [%4];" \
                 : "=r"(r0), "=r"(r1), "=r"(r2), "=r"(r3) : "r"(a))

#define MMA_BF16(c0, c1, c2, c3, a0, a1, a2, a3, b0, b1) \
    asm volatile("mma.sync.aligned.m16n8k16.row.col.f32.bf16.bf16.f32 " \
                 "{%0,%1,%2,%3}, {%4,%5,%6,%7}, {%8,%9}, {%0,%1,%2,%3};" \
                 : "+f"(c0), "+f"(c1), "+f"(c2), "+f"(c3) \
                 : "r"(a0), "r"(a1), "r"(a2), "r"(a3), "r"(b0), "r"(b1))

// ---------------- kernel 0: zero cluster sums ----------------
__global__ void k_zero() {
    int t = blockIdx.x * 256 + threadIdx.x;
    if (t < NCLU * CDIM) g_csum[t] = 0.f;
}

// ---------------- kernel 1: bilinear resize 24x24 -> 32x32 (writes V2^T) ----
__global__ void k_resize(const float* __restrict__ vext) {
    int col = blockIdx.x;                        // 0..767
    int n = blockIdx.y * 256 + threadIdx.x;      // 0..4095
    int h = col >> 6, d = col & 63;
    int b = n >> 10, s = n & 1023, yy = s >> 5, xx = s & 31;

    float sy = 0.75f * (float)yy - 0.125f;
    float sx = 0.75f * (float)xx - 0.125f;
    float fy0 = floorf(sy), fx0 = floorf(sx);
    int y0 = (int)fy0, x0 = (int)fx0;
    float fy = sy - fy0, fx = sx - fx0;
    int y0c = max(y0, 0), y1c = min(y0 + 1, 23);
    int x0c = max(x0, 0), x1c = min(x0 + 1, 23);

    const float* base = vext + ((size_t)(b * 12 + h)) * (24 * 24 * 64) + d;
    float v00 = base[(y0c * 24 + x0c) * 64];
    float v01 = base[(y0c * 24 + x1c) * 64];
    float v10 = base[(y1c * 24 + x0c) * 64];
    float v11 = base[(y1c * 24 + x1c) * 64];
    float top = v00 + fx * (v01 - v00);
    float bot = v10 + fx * (v11 - v10);
    float val = top + fy * (bot - top);

    __nv_bfloat16 hi = __float2bfloat16(val);
    float lo = val - __bfloat162float(hi);
    g_v2h[(size_t)col * N_TOK + n] = hi;
    g_v2l[(size_t)col * N_TOK + n] = __float2bfloat16(lo);
}

// ---------------- kernel 2: per-cluster feature sums ----------------
__global__ void k_csum(const float* __restrict__ x, const int* __restrict__ idx) {
    int t = blockIdx.x * 256 + threadIdx.x;
    int row = t / CDIM;
    int col = t - row * CDIM;
    int cl = __ldg(&idx[row]);
    atomicAdd(&g_csum[cl * CDIM + col], x[t]);
}

// ---------------- kernel 3: proxy + normalization (hi/lo bf16 out) ----------
__global__ __launch_bounds__(256) void k_proxy(const float* __restrict__ x,
                                               const int* __restrict__ idx) {
    __shared__ float red[256];
    int i = blockIdx.x, t = threadIdx.x;
    int ci = __ldg(&idx[i]);
    int b = i >> 10, s = i & 1023, r = s >> 5, c = s & 31;

    int nb[8];
    int nnb = 0;
#pragma unroll
    for (int dr = -1; dr <= 1; dr++) {
#pragma unroll
        for (int dc = -1; dc <= 1; dc++) {
            if (dr == 0 && dc == 0) continue;
            int rr = r + dr, cc = c + dc;
            if (rr >= 0 && rr < 32 && cc >= 0 && cc < 32) {
                int j = (b << 10) + (rr << 5) + cc;
                if (__ldg(&idx[j]) != ci) nb[nnb++] = j;
            }
        }
    }

    float p[3], xi[3];
#pragma unroll
    for (int u = 0; u < 3; u++) {
        int col = t + u * 256;
        float v = g_csum[ci * CDIM + col];
        for (int q = 0; q < nnb; q++) v += x[nb[q] * CDIM + col];
        p[u] = v;
        xi[u] = x[i * CDIM + col];
    }

    float ssp = p[0] * p[0] + p[1] * p[1] + p[2] * p[2];
    float ssx = xi[0] * xi[0] + xi[1] * xi[1] + xi[2] * xi[2];

    red[t] = ssp; __syncthreads();
    for (int w = 128; w > 0; w >>= 1) { if (t < w) red[t] += red[t + w]; __syncthreads(); }
    float SSP = red[0]; __syncthreads();
    red[t] = ssx; __syncthreads();
    for (int w = 128; w > 0; w >>= 1) { if (t < w) red[t] += red[t + w]; __syncthreads(); }
    float SSX = red[0];

    float ip = 1.f / fmaxf(sqrtf(SSP), 1e-12f);
    float ix = 1.f / fmaxf(sqrtf(SSX), 1e-12f);
#pragma unroll
    for (int u = 0; u < 3; u++) {
        int col = t + u * 256;
        float q = p[u] * ip;
        float k = xi[u] * ix;
        __nv_bfloat16 qh = __float2bfloat16(q);
        __nv_bfloat16 kh = __float2bfloat16(k);
        g_qnh[i * CDIM + col] = qh;
        g_qnl[i * CDIM + col] = __float2bfloat16(q - __bfloat162float(qh));
        g_knh[i * CDIM + col] = kh;
        g_knl[i * CDIM + col] = __float2bfloat16(k - __bfloat162float(kh));
    }
}

// ---------------- split-bf16 HMMA GEMM: C[M][N] = A[M][K] * B[N][K]^T -------
// MODE 0: SIM = QN @ KN^T  (K=768,  out g_sim fp32 ldc=4096)
// MODE 1: OUT = P  @ V2    (K=4096, out scatter rows, ldc=768)
// CTA tile 128x128, 8 warps (warp tile 32x64), K-chunk 32, 2-stage cp.async.
// SMEM per stage 32KB: Ah(8K) Al(8K) Bh(8K) Bl(8K); rows of 64B, XOR swizzle
// sw(r, c16) = c16 ^ ((r>>1)&3)  (conflict-free for ldmatrix + cp.async).
template <int MODE>
__global__ __launch_bounds__(256) void k_gemm_mma(float* __restrict__ outp) {
    extern __shared__ char smemc[];
    const int K = (MODE == 0) ? CDIM : N_TOK;
    const int NK = K / 32;
    const __nv_bfloat16* Ah = (MODE == 0) ? g_qnh : g_ph;
    const __nv_bfloat16* Al = (MODE == 0) ? g_qnl : g_pl;
    const __nv_bfloat16* Bh = (MODE == 0) ? g_knh : g_v2h;
    const __nv_bfloat16* Bl = (MODE == 0) ? g_knl : g_v2l;

    int tid = threadIdx.x;
    int bx = blockIdx.x, by = blockIdx.y;
    uint32_t sb = smem_u32(smemc);

    // ---- cp.async lane mapping: 2 threads/row, 2x16B each ----
    int lr = tid >> 1;                       // 0..127
    int lc0 = (tid & 1) * 2;                 // 16B-unit col 0 or 2
    size_t ga = (size_t)(by * 128 + lr) * K;
    size_t gb = (size_t)(bx * 128 + lr) * K;
    int xr = (lr >> 1) & 3;
    uint32_t so0 = lr * 64 + (((lc0 + 0) ^ xr) << 4);
    uint32_t so1 = lr * 64 + (((lc0 + 1) ^ xr) << 4);

    // ---- ldmatrix lane mapping ----
    int l = tid & 31, w = tid >> 5;
    int wm = w & 3, wn = w >> 2;             // warp tile: rows wm*32, cols wn*64
    int ra = wm * 32 + (l & 15);
    int xa = (ra >> 1) & 3;
    int ab = l >> 4;                          // 0/1 -> k-chunk halves
    uint32_t aoff = (uint32_t)ra * 64;
    int rb = wn * 64 + (l & 7) + ((l >> 4) & 1) * 8;
    int xb = (rb >> 1) & 3;
    int bb = (l >> 3) & 1;
    uint32_t boff = (uint32_t)rb * 64;

    float acc[2][8][4];
#pragma unroll
    for (int mt = 0; mt < 2; mt++)
#pragma unroll
        for (int nt = 0; nt < 8; nt++)
#pragma unroll
            for (int q = 0; q < 4; q++) acc[mt][nt][q] = 0.f;

#define ISSUE(kt_, s_) do {                                                    \
        uint32_t base_ = sb + (uint32_t)(s_) * 32768u;                         \
        const __nv_bfloat16* pa_  = Ah + ga + (kt_) * 32 + lc0 * 8;            \
        const __nv_bfloat16* pal_ = Al + ga + (kt_) * 32 + lc0 * 8;            \
        const __nv_bfloat16* pb_  = Bh + gb + (kt_) * 32 + lc0 * 8;            \
        const __nv_bfloat16* pbl_ = Bl + gb + (kt_) * 32 + lc0 * 8;            \
        CPA16(base_ + so0, pa_);            CPA16(base_ + so1, pa_ + 8);       \
        CPA16(base_ + 8192 + so0, pal_);    CPA16(base_ + 8192 + so1, pal_ + 8);\
        CPA16(base_ + 16384 + so0, pb_);    CPA16(base_ + 16384 + so1, pb_ + 8);\
        CPA16(base_ + 24576 + so0, pbl_);   CPA16(base_ + 24576 + so1, pbl_ + 8);\
        CP_COMMIT();                                                           \
    } while (0)

    ISSUE(0, 0);
    if (NK > 1) ISSUE(1, 1);

#pragma unroll 1
    for (int kt = 0; kt < NK; kt++) {
        if (kt + 1 < NK) { CP_WAIT(1); } else { CP_WAIT(0); }
        __syncthreads();
        uint32_t st = sb + (uint32_t)(kt & 1) * 32768u;
#pragma unroll
        for (int k16 = 0; k16 < 2; k16++) {
            uint32_t ah[2][4], al2[2][4];
#pragma unroll
            for (int mt = 0; mt < 2; mt++) {
                uint32_t ad = st + aoff + mt * 1024 + ((((2 * k16 + ab)) ^ xa) << 4);
                LDSM_X4(ah[mt][0], ah[mt][1], ah[mt][2], ah[mt][3], ad);
                LDSM_X4(al2[mt][0], al2[mt][1], al2[mt][2], al2[mt][3], ad + 8192);
            }
            uint32_t bh[4][4], bl2[4][4];
#pragma unroll
            for (int np = 0; np < 4; np++) {
                uint32_t bd = st + 16384 + boff + np * 1024 + ((((2 * k16 + bb)) ^ xb) << 4);
                LDSM_X4(bh[np][0], bh[np][1], bh[np][2], bh[np][3], bd);
                LDSM_X4(bl2[np][0], bl2[np][1], bl2[np][2], bl2[np][3], bd + 8192);
            }
#pragma unroll
            for (int mt = 0; mt < 2; mt++) {
#pragma unroll
                for (int nt = 0; nt < 8; nt++) {
                    int np = nt >> 1, h2 = (nt & 1) * 2;
                    float* C = acc[mt][nt];
                    MMA_BF16(C[0], C[1], C[2], C[3],
                             ah[mt][0], ah[mt][1], ah[mt][2], ah[mt][3],
                             bh[np][h2], bh[np][h2 + 1]);
                    MMA_BF16(C[0], C[1], C[2], C[3],
                             al2[mt][0], al2[mt][1], al2[mt][2], al2[mt][3],
                             bh[np][h2], bh[np][h2 + 1]);
                    MMA_BF16(C[0], C[1], C[2], C[3],
                             ah[mt][0], ah[mt][1], ah[mt][2], ah[mt][3],
                             bl2[np][h2], bl2[np][h2 + 1]);
                }
            }
        }
        __syncthreads();
        if (kt + 2 < NK) ISSUE(kt + 2, kt & 1);
    }
#undef ISSUE

    // ---- epilogue ----
    int l4 = l >> 2, l2 = (l & 3) * 2;
#pragma unroll
    for (int mt = 0; mt < 2; mt++) {
#pragma unroll
        for (int nt = 0; nt < 8; nt++) {
            int row0 = by * 128 + wm * 32 + mt * 16 + l4;
            int col = bx * 128 + wn * 64 + nt * 8 + l2;
            float2 v0 = make_float2(acc[mt][nt][0], acc[mt][nt][1]);
            float2 v1 = make_float2(acc[mt][nt][2], acc[mt][nt][3]);
            if (MODE == 0) {
                *(float2*)(g_sim + (size_t)row0 * N_TOK + col) = v0;
                *(float2*)(g_sim + (size_t)(row0 + 8) * N_TOK + col) = v1;
            } else {
                int o0 = (row0 & 1023) * 4 + (row0 >> 10);          // s*B + b
                int o1 = ((row0 + 8) & 1023) * 4 + ((row0 + 8) >> 10);
                *(float2*)(outp + (size_t)o0 * CDIM + col) = v0;
                *(float2*)(outp + (size_t)o1 * CDIM + col) = v1;
            }
        }
    }
}

// ---------------- softmax: token_norm + cut + softmax -> hi/lo bf16 probs ---
__global__ __launch_bounds__(256) void k_softmax() {
    __shared__ __align__(16) float rowbuf[N_TOK];
    __shared__ float red[256];
    int row = blockIdx.x, t = threadIdx.x;
    const float* Rp = g_sim + (size_t)row * N_TOK;

    float s = 0.f;
#pragma unroll
    for (int u = 0; u < 4; u++) {
        int c4 = t + u * 256;
        float4 v = ((const float4*)Rp)[c4];
        ((float4*)rowbuf)[c4] = v;
        s += (v.x + v.y) + (v.z + v.w);
    }
    red[t] = s; __syncthreads();
    for (int w = 128; w > 0; w >>= 1) { if (t < w) red[t] += red[t + w]; __syncthreads(); }
    float mean = fmaxf(red[0] * (1.f / 4096.f), 0.f);
    __syncthreads();

    float sub = mean * 1.2f;
    float mx = -3.402823466e38f;
#pragma unroll
    for (int u = 0; u < 4; u++) {
        int c4 = t + u * 256;
        float4 v = ((float4*)rowbuf)[c4];
        v.x = (v.x - sub) * 3.0f; v.y = (v.y - sub) * 3.0f;
        v.z = (v.z - sub) * 3.0f; v.w = (v.w - sub) * 3.0f;
        ((float4*)rowbuf)[c4] = v;
        mx = fmaxf(mx, fmaxf(fmaxf(v.x, v.y), fmaxf(v.z, v.w)));
    }
    red[t] = mx; __syncthreads();
    for (int w = 128; w > 0; w >>= 1) { if (t < w) red[t] = fmaxf(red[t], red[t + w]); __syncthreads(); }
    float M = red[0];
    __syncthreads();

    float cut = fminf(M, 0.1f);
    const float invT = 1.f / 0.07f;
    float zs = 0.f;
#pragma unroll
    for (int u = 0; u < 4; u++) {
        int c4 = t + u * 256;
        float4 v = ((float4*)rowbuf)[c4];
        v.x = (v.x < cut) ? 0.f : __expf((v.x - M) * invT);
        v.y = (v.y < cut) ? 0.f : __expf((v.y - M) * invT);
        v.z = (v.z < cut) ? 0.f : __expf((v.z - M) * invT);
        v.w = (v.w < cut) ? 0.f : __expf((v.w - M) * invT);
        ((float4*)rowbuf)[c4] = v;
        zs += (v.x + v.y) + (v.z + v.w);
    }
    red[t] = zs; __syncthreads();
    for (int w = 128; w > 0; w >>= 1) { if (t < w) red[t] += red[t + w]; __syncthreads(); }
    float inv = 1.f / red[0];

    __nv_bfloat16* Ph = g_ph + (size_t)row * N_TOK;
    __nv_bfloat16* Pl = g_pl + (size_t)row * N_TOK;
#pragma unroll
    for (int u = 0; u < 4; u++) {
        int c4 = t + u * 256;
        float4 v = ((float4*)rowbuf)[c4];
        v.x *= inv; v.y *= inv; v.z *= inv; v.w *= inv;
        __nv_bfloat16 hx = __float2bfloat16(v.x);
        __nv_bfloat16 hy = __float2bfloat16(v.y);
        __nv_bfloat16 hz = __float2bfloat16(v.z);
        __nv_bfloat16 hw = __float2bfloat16(v.w);
        *(__nv_bfloat162*)(Ph + c4 * 4)     = __halves2bfloat162(hx, hy);
        *(__nv_bfloat162*)(Ph + c4 * 4 + 2) = __halves2bfloat162(hz, hw);
        __nv_bfloat16 lx = __float2bfloat16(v.x - __bfloat162float(hx));
        __nv_bfloat16 ly = __float2bfloat16(v.y - __bfloat162float(hy));
        __nv_bfloat16 lz = __float2bfloat16(v.z - __bfloat162float(hz));
        __nv_bfloat16 lw = __float2bfloat16(v.w - __bfloat162float(hw));
        *(__nv_bfloat162*)(Pl + c4 * 4)     = __halves2bfloat162(lx, ly);
        *(__nv_bfloat162*)(Pl + c4 * 4 + 2) = __halves2bfloat162(lz, lw);
    }
}

// ---------------- launch ----------------
extern "C" void kernel_launch(void* const* d_in, const int* in_sizes, int n_in,
                              void* d_out, int out_size) {
    const float* ex = nullptr;
    const float* vext = nullptr;
    const int* idx = nullptr;
    for (int i = 0; i < n_in; i++) {
        if (in_sizes[i] == 4096) idx = (const int*)d_in[i];
        else if (in_sizes[i] == 2 * 2 * 1024 * 768) ex = (const float*)d_in[i];
        else if (in_sizes[i] == 48 * 24 * 24 * 64) vext = (const float*)d_in[i];
    }
    if (!ex || !vext || !idx) return;
    float* out = (float*)d_out;

    const int SMEM_GEMM = 2 * 32768;   // 2-stage double buffer
    cudaFuncSetAttribute(k_gemm_mma<0>, cudaFuncAttributeMaxDynamicSharedMemorySize, SMEM_GEMM);
    cudaFuncSetAttribute(k_gemm_mma<1>, cudaFuncAttributeMaxDynamicSharedMemorySize, SMEM_GEMM);

    k_zero<<<96, 256>>>();
    k_resize<<<dim3(768, 16), 256>>>(vext);
    k_csum<<<(N_TOK * CDIM) / 256, 256>>>(ex, idx);
    k_proxy<<<N_TOK, 256>>>(ex, idx);
    k_gemm_mma<0><<<dim3(32, 32), 256, SMEM_GEMM>>>(out);
    k_softmax<<<N_TOK, 256>>>();
    k_gemm_mma<1><<<dim3(6, 32), 256, SMEM_GEMM>>>(out);
}

// round 10
// speedup vs baseline: 2.2036x; 1.1713x over previous
#include <cuda_runtime.h>
#include <cuda_bf16.h>
#include <cstdint>
#include <math.h>

// ---------------- problem constants ----------------
#define N_TOK 4096     // B*S
#define CDIM  768      // C = nh*Dh
#define NCLU  32

// ---------------- scratch (static device memory; no allocs allowed) --------
__device__ __align__(256) float g_csum[NCLU * CDIM];
__device__ __align__(256) __nv_bfloat16 g_qnh[N_TOK * CDIM];   // l2norm(proxy) hi
__device__ __align__(256) __nv_bfloat16 g_qnl[N_TOK * CDIM];   // lo residual
__device__ __align__(256) __nv_bfloat16 g_knh[N_TOK * CDIM];   // l2norm(x) hi
__device__ __align__(256) __nv_bfloat16 g_knl[N_TOK * CDIM];
__device__ __align__(256) __nv_bfloat16 g_v2h[CDIM * N_TOK];   // resized V, TRANSPOSED [c][n]
__device__ __align__(256) __nv_bfloat16 g_v2l[CDIM * N_TOK];
__device__ __align__(256) float g_sim[(size_t)N_TOK * N_TOK];  // similarity (fp32)
__device__ __align__(256) __nv_bfloat16 g_ph[(size_t)N_TOK * N_TOK];  // probs hi
__device__ __align__(256) __nv_bfloat16 g_pl[(size_t)N_TOK * N_TOK];  // probs lo

// ---------------- PTX helpers (all baseline sm_80/75 features) -------------
__device__ __forceinline__ uint32_t smem_u32(const void* p) {
    uint32_t a;
    asm("{ .reg .u64 t; cvta.to.shared.u64 t, %1; cvt.u32.u64 %0, t; }" : "=r"(a) : "l"(p));
    return a;
}
#define CPA16(dst, src) \
    asm volatile("cp.async.cg.shared.global [%0], [%1], 16;" :: "r"(dst), "l"(src))
#define CP_COMMIT() asm volatile("cp.async.commit_group;")
#define CP_WAIT(n)  asm volatile("cp.async.wait_group %0;" :: "n"(n))

#define LDSM_X4(r0, r1, r2, r3, a) \
    asm volatile("ldmatrix.sync.aligned.m8n8.x4.shared.b16 {%0,%1,%2,%3}, [%4];" \
                 : "=r"(r0), "=r"(r1), "=r"(r2), "=r"(r3) : "r"(a))

#define MMA_BF16(c0, c1, c2, c3, a0, a1, a2, a3, b0, b1) \
    asm volatile("mma.sync.aligned.m16n8k16.row.col.f32.bf16.bf16.f32 " \
                 "{%0,%1,%2,%3}, {%4,%5,%6,%7}, {%8,%9}, {%0,%1,%2,%3};" \
                 : "+f"(c0), "+f"(c1), "+f"(c2), "+f"(c3) \
                 : "r"(a0), "r"(a1), "r"(a2), "r"(a3), "r"(b0), "r"(b1))

// FFMA-only exp for t <= 0 (rel err ~3e-7): exp(t) = 2^n * poly(f)
__device__ __forceinline__ float fexp(float t) {
    float z = t * 1.4426950408889634f;      // log2(e)
    z = fmaxf(z, -126.0f);
    float n = floorf(z);
    float f = z - n;
    float p = 1.33336498e-3f;
    p = fmaf(p, f, 9.61817017e-3f);
    p = fmaf(p, f, 5.55036049e-2f);
    p = fmaf(p, f, 2.40226507e-1f);
    p = fmaf(p, f, 6.93147182e-1f);
    p = fmaf(p, f, 1.0f);
    int ni = (int)n;
    float sc = __int_as_float((ni + 127) << 23);
    return p * sc;
}

// ---------------- kernel 0: zero cluster sums ----------------
__global__ void k_zero() {
    int t = blockIdx.x * 256 + threadIdx.x;
    if (t < NCLU * CDIM) g_csum[t] = 0.f;
}

// ---------------- kernel 1: bilinear resize 24x24 -> 32x32 (writes V2^T) ----
__global__ void k_resize(const float* __restrict__ vext) {
    int col = blockIdx.x;                        // 0..767
    int n = blockIdx.y * 256 + threadIdx.x;      // 0..4095
    int h = col >> 6, d = col & 63;
    int b = n >> 10, s = n & 1023, yy = s >> 5, xx = s & 31;

    float sy = 0.75f * (float)yy - 0.125f;
    float sx = 0.75f * (float)xx - 0.125f;
    float fy0 = floorf(sy), fx0 = floorf(sx);
    int y0 = (int)fy0, x0 = (int)fx0;
    float fy = sy - fy0, fx = sx - fx0;
    int y0c = max(y0, 0), y1c = min(y0 + 1, 23);
    int x0c = max(x0, 0), x1c = min(x0 + 1, 23);

    const float* base = vext + ((size_t)(b * 12 + h)) * (24 * 24 * 64) + d;
    float v00 = base[(y0c * 24 + x0c) * 64];
    float v01 = base[(y0c * 24 + x1c) * 64];
    float v10 = base[(y1c * 24 + x0c) * 64];
    float v11 = base[(y1c * 24 + x1c) * 64];
    float top = v00 + fx * (v01 - v00);
    float bot = v10 + fx * (v11 - v10);
    float val = top + fy * (bot - top);

    __nv_bfloat16 hi = __float2bfloat16(val);
    float lo = val - __bfloat162float(hi);
    g_v2h[(size_t)col * N_TOK + n] = hi;
    g_v2l[(size_t)col * N_TOK + n] = __float2bfloat16(lo);
}

// ---------------- kernel 2: per-cluster feature sums ----------------
__global__ void k_csum(const float* __restrict__ x, const int* __restrict__ idx) {
    int t = blockIdx.x * 256 + threadIdx.x;
    int row = t / CDIM;
    int col = t - row * CDIM;
    int cl = __ldg(&idx[row]);
    atomicAdd(&g_csum[cl * CDIM + col], x[t]);
}

// ---------------- kernel 3: proxy + normalization (hi/lo bf16 out) ----------
__global__ __launch_bounds__(256) void k_proxy(const float* __restrict__ x,
                                               const int* __restrict__ idx) {
    __shared__ float red[256];
    int i = blockIdx.x, t = threadIdx.x;
    int ci = __ldg(&idx[i]);
    int b = i >> 10, s = i & 1023, r = s >> 5, c = s & 31;

    int nb[8];
    int nnb = 0;
#pragma unroll
    for (int dr = -1; dr <= 1; dr++) {
#pragma unroll
        for (int dc = -1; dc <= 1; dc++) {
            if (dr == 0 && dc == 0) continue;
            int rr = r + dr, cc = c + dc;
            if (rr >= 0 && rr < 32 && cc >= 0 && cc < 32) {
                int j = (b << 10) + (rr << 5) + cc;
                if (__ldg(&idx[j]) != ci) nb[nnb++] = j;
            }
        }
    }

    float p[3], xi[3];
#pragma unroll
    for (int u = 0; u < 3; u++) {
        int col = t + u * 256;
        float v = g_csum[ci * CDIM + col];
        for (int q = 0; q < nnb; q++) v += x[nb[q] * CDIM + col];
        p[u] = v;
        xi[u] = x[i * CDIM + col];
    }

    float ssp = p[0] * p[0] + p[1] * p[1] + p[2] * p[2];
    float ssx = xi[0] * xi[0] + xi[1] * xi[1] + xi[2] * xi[2];

    red[t] = ssp; __syncthreads();
    for (int w = 128; w > 0; w >>= 1) { if (t < w) red[t] += red[t + w]; __syncthreads(); }
    float SSP = red[0]; __syncthreads();
    red[t] = ssx; __syncthreads();
    for (int w = 128; w > 0; w >>= 1) { if (t < w) red[t] += red[t + w]; __syncthreads(); }
    float SSX = red[0];

    float ip = 1.f / fmaxf(sqrtf(SSP), 1e-12f);
    float ix = 1.f / fmaxf(sqrtf(SSX), 1e-12f);
#pragma unroll
    for (int u = 0; u < 3; u++) {
        int col = t + u * 256;
        float q = p[u] * ip;
        float k = xi[u] * ix;
        __nv_bfloat16 qh = __float2bfloat16(q);
        __nv_bfloat16 kh = __float2bfloat16(k);
        g_qnh[i * CDIM + col] = qh;
        g_qnl[i * CDIM + col] = __float2bfloat16(q - __bfloat162float(qh));
        g_knh[i * CDIM + col] = kh;
        g_knl[i * CDIM + col] = __float2bfloat16(k - __bfloat162float(kh));
    }
}

// ---------------- split-bf16 HMMA GEMM: C[M][N] = A[M][K] * B[N][K]^T -------
// MODE 0: SIM = QN @ KN^T  (K=768,  NTILE=128, occ1) -> g_sim fp32
// MODE 1: OUT = P  @ V2    (K=4096, NTILE=96,  occ2) -> scatter rows
// CTA tile 128 x NTILE, 8 warps (4x2), warp tile 32 x NTILE/2, K-chunk 32,
// 2-stage cp.async. XOR swizzle sw(r,c16)=c16^((r>>1)&3).
template <int MODE, int NTILE>
__global__ __launch_bounds__(256, (MODE == 1) ? 2 : 1)
void k_gemm_mma(float* __restrict__ outp) {
    extern __shared__ char smemc[];
    const int K = (MODE == 0) ? CDIM : N_TOK;
    const int NK = K / 32;
    const int NP = NTILE / 32;          // 16-row LDSM groups per warp-col
    const int NT = 2 * NP;              // 8-col accum tiles per warp
    const int BH_OFF = 16384;
    const int BL_OFF = 16384 + NTILE * 64;
    const int STAGE = 16384 + 2 * NTILE * 64;

    const __nv_bfloat16* Ah = (MODE == 0) ? g_qnh : g_ph;
    const __nv_bfloat16* Al = (MODE == 0) ? g_qnl : g_pl;
    const __nv_bfloat16* Bh = (MODE == 0) ? g_knh : g_v2h;
    const __nv_bfloat16* Bl = (MODE == 0) ? g_knl : g_v2l;

    int tid = threadIdx.x;
    int bx = blockIdx.x, by = blockIdx.y;
    uint32_t sb = smem_u32(smemc);

    // ---- cp.async lane mapping: 2 threads/row, 2x16B each ----
    int lr = tid >> 1;                       // 0..127
    int lc0 = (tid & 1) * 2;                 // 16B-unit col 0 or 2
    size_t ga = (size_t)(by * 128 + lr) * K;
    size_t gb = (size_t)(bx * NTILE + lr) * K;
    int xr = (lr >> 1) & 3;
    uint32_t so0 = lr * 64 + (((lc0 + 0) ^ xr) << 4);
    uint32_t so1 = lr * 64 + (((lc0 + 1) ^ xr) << 4);

    // ---- ldmatrix lane mapping ----
    int l = tid & 31, w = tid >> 5;
    int wm = w & 3, wn = w >> 2;             // warp tile: rows wm*32, cols wn*(NTILE/2)
    int ra = wm * 32 + (l & 15);
    int xa = (ra >> 1) & 3;
    int ab = l >> 4;
    uint32_t aoff = (uint32_t)ra * 64;
    int rb = wn * (NTILE / 2) + (l & 7) + ((l >> 4) & 1) * 8;
    int xb = (rb >> 1) & 3;
    int bb = (l >> 3) & 1;
    uint32_t boff = (uint32_t)rb * 64;

    float acc[2][NT][4];
#pragma unroll
    for (int mt = 0; mt < 2; mt++)
#pragma unroll
        for (int nt = 0; nt < NT; nt++)
#pragma unroll
            for (int q = 0; q < 4; q++) acc[mt][nt][q] = 0.f;

#define ISSUE(kt_, s_) do {                                                    \
        uint32_t base_ = sb + (uint32_t)(s_) * STAGE;                          \
        const __nv_bfloat16* pa_  = Ah + ga + (kt_) * 32 + lc0 * 8;            \
        const __nv_bfloat16* pal_ = Al + ga + (kt_) * 32 + lc0 * 8;            \
        CPA16(base_ + so0, pa_);           CPA16(base_ + so1, pa_ + 8);        \
        CPA16(base_ + 8192 + so0, pal_);   CPA16(base_ + 8192 + so1, pal_ + 8);\
        if (lr < NTILE) {                                                      \
            const __nv_bfloat16* pb_  = Bh + gb + (kt_) * 32 + lc0 * 8;        \
            const __nv_bfloat16* pbl_ = Bl + gb + (kt_) * 32 + lc0 * 8;        \
            CPA16(base_ + BH_OFF + so0, pb_);                                  \
            CPA16(base_ + BH_OFF + so1, pb_ + 8);                              \
            CPA16(base_ + BL_OFF + so0, pbl_);                                 \
            CPA16(base_ + BL_OFF + so1, pbl_ + 8);                             \
        }                                                                      \
        CP_COMMIT();                                                           \
    } while (0)

    ISSUE(0, 0);
    if (NK > 1) ISSUE(1, 1);

#pragma unroll 1
    for (int kt = 0; kt < NK; kt++) {
        if (kt + 1 < NK) { CP_WAIT(1); } else { CP_WAIT(0); }
        __syncthreads();
        uint32_t st = sb + (uint32_t)(kt & 1) * STAGE;
#pragma unroll
        for (int k16 = 0; k16 < 2; k16++) {
            uint32_t ah[2][4], al2[2][4];
#pragma unroll
            for (int mt = 0; mt < 2; mt++) {
                uint32_t ad = st + aoff + mt * 1024 + ((((2 * k16 + ab)) ^ xa) << 4);
                LDSM_X4(ah[mt][0], ah[mt][1], ah[mt][2], ah[mt][3], ad);
                LDSM_X4(al2[mt][0], al2[mt][1], al2[mt][2], al2[mt][3], ad + 8192);
            }
            uint32_t bh[NP][4], bl2[NP][4];
#pragma unroll
            for (int np = 0; np < NP; np++) {
                uint32_t bd = st + BH_OFF + boff + np * 1024 + ((((2 * k16 + bb)) ^ xb) << 4);
                LDSM_X4(bh[np][0], bh[np][1], bh[np][2], bh[np][3], bd);
                LDSM_X4(bl2[np][0], bl2[np][1], bl2[np][2], bl2[np][3], bd + NTILE * 64);
            }
#pragma unroll
            for (int mt = 0; mt < 2; mt++) {
#pragma unroll
                for (int nt = 0; nt < NT; nt++) {
                    int np = nt >> 1, h2 = (nt & 1) * 2;
                    float* C = acc[mt][nt];
                    MMA_BF16(C[0], C[1], C[2], C[3],
                             ah[mt][0], ah[mt][1], ah[mt][2], ah[mt][3],
                             bh[np][h2], bh[np][h2 + 1]);
                    MMA_BF16(C[0], C[1], C[2], C[3],
                             al2[mt][0], al2[mt][1], al2[mt][2], al2[mt][3],
                             bh[np][h2], bh[np][h2 + 1]);
                    MMA_BF16(C[0], C[1], C[2], C[3],
                             ah[mt][0], ah[mt][1], ah[mt][2], ah[mt][3],
                             bl2[np][h2], bl2[np][h2 + 1]);
                }
            }
        }
        __syncthreads();
        if (kt + 2 < NK) ISSUE(kt + 2, kt & 1);
    }
#undef ISSUE

    // ---- epilogue ----
    int l4 = l >> 2, l2 = (l & 3) * 2;
#pragma unroll
    for (int mt = 0; mt < 2; mt++) {
#pragma unroll
        for (int nt = 0; nt < NT; nt++) {
            int row0 = by * 128 + wm * 32 + mt * 16 + l4;
            int col = bx * NTILE + wn * (NTILE / 2) + nt * 8 + l2;
            float2 v0 = make_float2(acc[mt][nt][0], acc[mt][nt][1]);
            float2 v1 = make_float2(acc[mt][nt][2], acc[mt][nt][3]);
            if (MODE == 0) {
                *(float2*)(g_sim + (size_t)row0 * N_TOK + col) = v0;
                *(float2*)(g_sim + (size_t)(row0 + 8) * N_TOK + col) = v1;
            } else {
                int o0 = (row0 & 1023) * 4 + (row0 >> 10);          // s*B + b
                int o1 = ((row0 + 8) & 1023) * 4 + ((row0 + 8) >> 10);
                *(float2*)(outp + (size_t)o0 * CDIM + col) = v0;
                *(float2*)(outp + (size_t)o1 * CDIM + col) = v1;
            }
        }
    }
}

// ---------------- block reductions (8 warps) ----------------
__device__ __forceinline__ float bred_sum(float v, float* wred, int t) {
#pragma unroll
    for (int o = 16; o > 0; o >>= 1) v += __shfl_xor_sync(0xffffffffu, v, o);
    __syncthreads();
    if ((t & 31) == 0) wred[t >> 5] = v;
    __syncthreads();
    float s = 0.f;
#pragma unroll
    for (int i = 0; i < 8; i++) s += wred[i];
    return s;
}
__device__ __forceinline__ float bred_max(float v, float* wred, int t) {
#pragma unroll
    for (int o = 16; o > 0; o >>= 1) v = fmaxf(v, __shfl_xor_sync(0xffffffffu, v, o));
    __syncthreads();
    if ((t & 31) == 0) wred[t >> 5] = v;
    __syncthreads();
    float s = -3.402823466e38f;
#pragma unroll
    for (int i = 0; i < 8; i++) s = fmaxf(s, wred[i]);
    return s;
}

// ---------------- softmax: token_norm + cut + softmax -> hi/lo bf16 probs ---
// Row kept entirely in registers (16 floats/thread); FFMA-poly exp (no MUFU).
__global__ __launch_bounds__(256) void k_softmax() {
    __shared__ float wred[8];
    int row = blockIdx.x, t = threadIdx.x;
    const float* Rp = g_sim + (size_t)row * N_TOK;

    float4 va[4];
    float s = 0.f;
#pragma unroll
    for (int u = 0; u < 4; u++) {
        va[u] = ((const float4*)Rp)[t + u * 256];
        s += (va[u].x + va[u].y) + (va[u].z + va[u].w);
    }
    float mean = fmaxf(bred_sum(s, wred, t) * (1.f / 4096.f), 0.f);

    float sub = mean * 1.2f;
    float mx = -3.402823466e38f;
#pragma unroll
    for (int u = 0; u < 4; u++) {
        va[u].x = (va[u].x - sub) * 3.0f; va[u].y = (va[u].y - sub) * 3.0f;
        va[u].z = (va[u].z - sub) * 3.0f; va[u].w = (va[u].w - sub) * 3.0f;
        mx = fmaxf(mx, fmaxf(fmaxf(va[u].x, va[u].y), fmaxf(va[u].z, va[u].w)));
    }
    float M = bred_max(mx, wred, t);

    float cut = fminf(M, 0.1f);
    const float invT = 1.f / 0.07f;
    float zs = 0.f;
#pragma unroll
    for (int u = 0; u < 4; u++) {
        va[u].x = (va[u].x < cut) ? 0.f : fexp((va[u].x - M) * invT);
        va[u].y = (va[u].y < cut) ? 0.f : fexp((va[u].y - M) * invT);
        va[u].z = (va[u].z < cut) ? 0.f : fexp((va[u].z - M) * invT);
        va[u].w = (va[u].w < cut) ? 0.f : fexp((va[u].w - M) * invT);
        zs += (va[u].x + va[u].y) + (va[u].z + va[u].w);
    }
    float inv = 1.f / bred_sum(zs, wred, t);

    __nv_bfloat16* Ph = g_ph + (size_t)row * N_TOK;
    __nv_bfloat16* Pl = g_pl + (size_t)row * N_TOK;
#pragma unroll
    for (int u = 0; u < 4; u++) {
        int c4 = t + u * 256;
        float x0 = va[u].x * inv, x1 = va[u].y * inv;
        float x2 = va[u].z * inv, x3 = va[u].w * inv;
        __nv_bfloat16 h0 = __float2bfloat16(x0);
        __nv_bfloat16 h1 = __float2bfloat16(x1);
        __nv_bfloat16 h2 = __float2bfloat16(x2);
        __nv_bfloat16 h3 = __float2bfloat16(x3);
        *(__nv_bfloat162*)(Ph + c4 * 4)     = __halves2bfloat162(h0, h1);
        *(__nv_bfloat162*)(Ph + c4 * 4 + 2) = __halves2bfloat162(h2, h3);
        __nv_bfloat16 l0 = __float2bfloat16(x0 - __bfloat162float(h0));
        __nv_bfloat16 l1 = __float2bfloat16(x1 - __bfloat162float(h1));
        __nv_bfloat16 l2b = __float2bfloat16(x2 - __bfloat162float(h2));
        __nv_bfloat16 l3 = __float2bfloat16(x3 - __bfloat162float(h3));
        *(__nv_bfloat162*)(Pl + c4 * 4)     = __halves2bfloat162(l0, l1);
        *(__nv_bfloat162*)(Pl + c4 * 4 + 2) = __halves2bfloat162(l2b, l3);
    }
}

// ---------------- launch ----------------
extern "C" void kernel_launch(void* const* d_in, const int* in_sizes, int n_in,
                              void* d_out, int out_size) {
    const float* ex = nullptr;
    const float* vext = nullptr;
    const int* idx = nullptr;
    for (int i = 0; i < n_in; i++) {
        if (in_sizes[i] == 4096) idx = (const int*)d_in[i];
        else if (in_sizes[i] == 2 * 2 * 1024 * 768) ex = (const float*)d_in[i];
        else if (in_sizes[i] == 48 * 24 * 24 * 64) vext = (const float*)d_in[i];
    }
    if (!ex || !vext || !idx) return;
    float* out = (float*)d_out;

    const int SMEM_G1 = 2 * 32768;                 // NTILE=128 stages
    const int SMEM_G2 = 2 * (16384 + 2 * 96 * 64); // NTILE=96 stages (57344)
    cudaFuncSetAttribute(k_gemm_mma<0, 128>, cudaFuncAttributeMaxDynamicSharedMemorySize, SMEM_G1);
    cudaFuncSetAttribute(k_gemm_mma<1, 96>, cudaFuncAttributeMaxDynamicSharedMemorySize, SMEM_G2);

    k_zero<<<96, 256>>>();
    k_resize<<<dim3(768, 16), 256>>>(vext);
    k_csum<<<(N_TOK * CDIM) / 256, 256>>>(ex, idx);
    k_proxy<<<N_TOK, 256>>>(ex, idx);
    k_gemm_mma<0, 128><<<dim3(32, 32), 256, SMEM_G1>>>(out);
    k_softmax<<<N_TOK, 256>>>();
    k_gemm_mma<1, 96><<<dim3(8, 32), 256, SMEM_G2>>>(out);
}

// round 11
// speedup vs baseline: 2.3251x; 1.0551x over previous
#include <cuda_runtime.h>
#include <cuda_bf16.h>
#include <cstdint>
#include <math.h>

// ---------------- problem constants ----------------
#define N_TOK 4096     // B*S
#define CDIM  768      // C = nh*Dh
#define NCLU  32

// ---------------- scratch (static device memory; no allocs allowed) --------
__device__ __align__(256) float g_csum[NCLU * CDIM];
__device__ __align__(256) __nv_bfloat16 g_qnh[N_TOK * CDIM];   // l2norm(proxy) hi
__device__ __align__(256) __nv_bfloat16 g_qnl[N_TOK * CDIM];   // lo residual
__device__ __align__(256) __nv_bfloat16 g_knh[N_TOK * CDIM];   // l2norm(x) hi
__device__ __align__(256) __nv_bfloat16 g_knl[N_TOK * CDIM];
__device__ __align__(256) __nv_bfloat16 g_v2h[CDIM * N_TOK];   // resized V, TRANSPOSED [c][n]
__device__ __align__(256) __nv_bfloat16 g_v2l[CDIM * N_TOK];
__device__ __align__(256) float g_sim[(size_t)N_TOK * N_TOK];  // similarity (fp32)
__device__ __align__(256) __nv_bfloat16 g_ph[(size_t)N_TOK * N_TOK];  // probs hi
__device__ __align__(256) __nv_bfloat16 g_pl[(size_t)N_TOK * N_TOK];  // probs lo

// ---------------- PTX helpers (all baseline sm_80/89 features) -------------
__device__ __forceinline__ uint32_t smem_u32(const void* p) {
    uint32_t a;
    asm("{ .reg .u64 t; cvta.to.shared.u64 t, %1; cvt.u32.u64 %0, t; }" : "=r"(a) : "l"(p));
    return a;
}
#define CPA16(dst, src) \
    asm volatile("cp.async.cg.shared.global [%0], [%1], 16;" :: "r"(dst), "l"(src))
#define CP_COMMIT() asm volatile("cp.async.commit_group;")
#define CP_WAIT(n)  asm volatile("cp.async.wait_group %0;" :: "n"(n))

#define LDSM_X4(r0, r1, r2, r3, a) \
    asm volatile("ldmatrix.sync.aligned.m8n8.x4.shared.b16 {%0,%1,%2,%3}, [%4];" \
                 : "=r"(r0), "=r"(r1), "=r"(r2), "=r"(r3) : "r"(a))

#define MMA_BF16(c0, c1, c2, c3, a0, a1, a2, a3, b0, b1) \
    asm volatile("mma.sync.aligned.m16n8k16.row.col.f32.bf16.bf16.f32 " \
                 "{%0,%1,%2,%3}, {%4,%5,%6,%7}, {%8,%9}, {%0,%1,%2,%3};" \
                 : "+f"(c0), "+f"(c1), "+f"(c2), "+f"(c3) \
                 : "r"(a0), "r"(a1), "r"(a2), "r"(a3), "r"(b0), "r"(b1))

// FFMA-only exp for t <= 0 (rel err ~3e-7): exp(t) = 2^n * poly(f)
__device__ __forceinline__ float fexp(float t) {
    float z = t * 1.4426950408889634f;      // log2(e)
    z = fmaxf(z, -126.0f);
    float n = floorf(z);
    float f = z - n;
    float p = 1.33336498e-3f;
    p = fmaf(p, f, 9.61817017e-3f);
    p = fmaf(p, f, 5.55036049e-2f);
    p = fmaf(p, f, 2.40226507e-1f);
    p = fmaf(p, f, 6.93147182e-1f);
    p = fmaf(p, f, 1.0f);
    int ni = (int)n;
    float sc = __int_as_float((ni + 127) << 23);
    return p * sc;
}

// ---------------- kernel 0: zero cluster sums ----------------
__global__ void k_zero() {
    int t = blockIdx.x * 256 + threadIdx.x;
    if (t < NCLU * CDIM) g_csum[t] = 0.f;
}

// ---------------- kernel 1: bilinear resize 24x24 -> 32x32 (writes V2^T) ----
__global__ void k_resize(const float* __restrict__ vext) {
    int col = blockIdx.x;                        // 0..767
    int n = blockIdx.y * 256 + threadIdx.x;      // 0..4095
    int h = col >> 6, d = col & 63;
    int b = n >> 10, s = n & 1023, yy = s >> 5, xx = s & 31;

    float sy = 0.75f * (float)yy - 0.125f;
    float sx = 0.75f * (float)xx - 0.125f;
    float fy0 = floorf(sy), fx0 = floorf(sx);
    int y0 = (int)fy0, x0 = (int)fx0;
    float fy = sy - fy0, fx = sx - fx0;
    int y0c = max(y0, 0), y1c = min(y0 + 1, 23);
    int x0c = max(x0, 0), x1c = min(x0 + 1, 23);

    const float* base = vext + ((size_t)(b * 12 + h)) * (24 * 24 * 64) + d;
    float v00 = base[(y0c * 24 + x0c) * 64];
    float v01 = base[(y0c * 24 + x1c) * 64];
    float v10 = base[(y1c * 24 + x0c) * 64];
    float v11 = base[(y1c * 24 + x1c) * 64];
    float top = v00 + fx * (v01 - v00);
    float bot = v10 + fx * (v11 - v10);
    float val = top + fy * (bot - top);

    __nv_bfloat16 hi = __float2bfloat16(val);
    float lo = val - __bfloat162float(hi);
    g_v2h[(size_t)col * N_TOK + n] = hi;
    g_v2l[(size_t)col * N_TOK + n] = __float2bfloat16(lo);
}

// ---------------- kernel 2: per-cluster feature sums (smem-staged) ----------
// grid (16, 3): block = rows [256*bx, 256*bx+256) x cols [256*by, 256*by+256)
__global__ __launch_bounds__(256) void k_csum(const float* __restrict__ x,
                                              const int* __restrict__ idx) {
    __shared__ float sacc[NCLU * 256];           // 32 KB
    __shared__ int sidx[256];
    int t = threadIdx.x;
    int r0 = blockIdx.x * 256;
    int c0 = blockIdx.y * 256;

#pragma unroll
    for (int c = 0; c < NCLU; c++) sacc[c * 256 + t] = 0.f;
    sidx[t] = idx[r0 + t];
    __syncthreads();

    // column t is owned by thread t -> no concurrent writers, plain RMW
    const float* xp = x + (size_t)r0 * CDIM + c0 + t;
#pragma unroll 4
    for (int r = 0; r < 256; r++) {
        int cl = sidx[r];
        sacc[cl * 256 + t] += xp[(size_t)r * CDIM];
    }
    __syncthreads();

#pragma unroll
    for (int c = 0; c < NCLU; c++)
        atomicAdd(&g_csum[c * CDIM + c0 + t], sacc[c * 256 + t]);
}

// ---------------- kernel 3: proxy + normalization (hi/lo bf16 out) ----------
__global__ __launch_bounds__(256) void k_proxy(const float* __restrict__ x,
                                               const int* __restrict__ idx) {
    __shared__ float red[256];
    int i = blockIdx.x, t = threadIdx.x;
    int ci = __ldg(&idx[i]);
    int b = i >> 10, s = i & 1023, r = s >> 5, c = s & 31;

    int nb[8];
    int nnb = 0;
#pragma unroll
    for (int dr = -1; dr <= 1; dr++) {
#pragma unroll
        for (int dc = -1; dc <= 1; dc++) {
            if (dr == 0 && dc == 0) continue;
            int rr = r + dr, cc = c + dc;
            if (rr >= 0 && rr < 32 && cc >= 0 && cc < 32) {
                int j = (b << 10) + (rr << 5) + cc;
                if (__ldg(&idx[j]) != ci) nb[nnb++] = j;
            }
        }
    }

    float p[3], xi[3];
#pragma unroll
    for (int u = 0; u < 3; u++) {
        int col = t + u * 256;
        float v = g_csum[ci * CDIM + col];
        for (int q = 0; q < nnb; q++) v += x[nb[q] * CDIM + col];
        p[u] = v;
        xi[u] = x[i * CDIM + col];
    }

    float ssp = p[0] * p[0] + p[1] * p[1] + p[2] * p[2];
    float ssx = xi[0] * xi[0] + xi[1] * xi[1] + xi[2] * xi[2];

    red[t] = ssp; __syncthreads();
    for (int w = 128; w > 0; w >>= 1) { if (t < w) red[t] += red[t + w]; __syncthreads(); }
    float SSP = red[0]; __syncthreads();
    red[t] = ssx; __syncthreads();
    for (int w = 128; w > 0; w >>= 1) { if (t < w) red[t] += red[t + w]; __syncthreads(); }
    float SSX = red[0];

    float ip = 1.f / fmaxf(sqrtf(SSP), 1e-12f);
    float ix = 1.f / fmaxf(sqrtf(SSX), 1e-12f);
#pragma unroll
    for (int u = 0; u < 3; u++) {
        int col = t + u * 256;
        float q = p[u] * ip;
        float k = xi[u] * ix;
        __nv_bfloat16 qh = __float2bfloat16(q);
        __nv_bfloat16 kh = __float2bfloat16(k);
        g_qnh[i * CDIM + col] = qh;
        g_qnl[i * CDIM + col] = __float2bfloat16(q - __bfloat162float(qh));
        g_knh[i * CDIM + col] = kh;
        g_knl[i * CDIM + col] = __float2bfloat16(k - __bfloat162float(kh));
    }
}

// ---------------- split-bf16 HMMA GEMM: C[M][N] = A[M][K] * B[N][K]^T -------
// MODE 0: SIM = QN @ KN^T  (K=768,  NTILE=128) -> g_sim fp32
// MODE 1: OUT = P  @ V2    (K=4096, NTILE=96)  -> scatter rows
// CTA tile 128 x NTILE, 8 warps (4x2), K-chunk 32, 3-stage cp.async pipeline
// with ONE __syncthreads per chunk. Both kernels occ 2 (128-reg cap; inner
// loop holds a single B-fragment pair to fit).
// XOR swizzle sw(r,c16)=c16^((r>>1)&3).
template <int MODE, int NTILE>
__global__ __launch_bounds__(256, 2)
void k_gemm_mma(float* __restrict__ outp) {
    extern __shared__ char smemc[];
    const int K = (MODE == 0) ? CDIM : N_TOK;
    const int NK = K / 32;
    const int NP = NTILE / 32;          // 16-row LDSM groups per warp-col
    const int NT = 2 * NP;              // 8-col accum tiles per warp
    const int BH_OFF = 16384;
    const int BL_OFF = 16384 + NTILE * 64;
    const int STAGE = 16384 + 2 * NTILE * 64;

    const __nv_bfloat16* Ah = (MODE == 0) ? g_qnh : g_ph;
    const __nv_bfloat16* Al = (MODE == 0) ? g_qnl : g_pl;
    const __nv_bfloat16* Bh = (MODE == 0) ? g_knh : g_v2h;
    const __nv_bfloat16* Bl = (MODE == 0) ? g_knl : g_v2l;

    int tid = threadIdx.x;
    int bx = blockIdx.x, by = blockIdx.y;
    uint32_t sb = smem_u32(smemc);

    // ---- cp.async lane mapping: 2 threads/row, 2x16B each ----
    int lr = tid >> 1;                       // 0..127
    int lc0 = (tid & 1) * 2;                 // 16B-unit col 0 or 2
    size_t ga = (size_t)(by * 128 + lr) * K;
    size_t gb = (size_t)(bx * NTILE + lr) * K;
    int xr = (lr >> 1) & 3;
    uint32_t so0 = lr * 64 + (((lc0 + 0) ^ xr) << 4);
    uint32_t so1 = lr * 64 + (((lc0 + 1) ^ xr) << 4);

    // ---- ldmatrix lane mapping ----
    int l = tid & 31, w = tid >> 5;
    int wm = w & 3, wn = w >> 2;             // warp tile: rows wm*32, cols wn*(NTILE/2)
    int ra = wm * 32 + (l & 15);
    int xa = (ra >> 1) & 3;
    int ab = l >> 4;
    uint32_t aoff = (uint32_t)ra * 64;
    int rb = wn * (NTILE / 2) + (l & 7) + ((l >> 4) & 1) * 8;
    int xb = (rb >> 1) & 3;
    int bb = (l >> 3) & 1;
    uint32_t boff = (uint32_t)rb * 64;

    float acc[2][NT][4];
#pragma unroll
    for (int mt = 0; mt < 2; mt++)
#pragma unroll
        for (int nt = 0; nt < NT; nt++)
#pragma unroll
            for (int q = 0; q < 4; q++) acc[mt][nt][q] = 0.f;

#define ISSUE(kt_, s_) do {                                                    \
        uint32_t base_ = sb + (uint32_t)(s_) * STAGE;                          \
        const __nv_bfloat16* pa_  = Ah + ga + (kt_) * 32 + lc0 * 8;            \
        const __nv_bfloat16* pal_ = Al + ga + (kt_) * 32 + lc0 * 8;            \
        CPA16(base_ + so0, pa_);           CPA16(base_ + so1, pa_ + 8);        \
        CPA16(base_ + 8192 + so0, pal_);   CPA16(base_ + 8192 + so1, pal_ + 8);\
        if (lr < NTILE) {                                                      \
            const __nv_bfloat16* pb_  = Bh + gb + (kt_) * 32 + lc0 * 8;        \
            const __nv_bfloat16* pbl_ = Bl + gb + (kt_) * 32 + lc0 * 8;        \
            CPA16(base_ + BH_OFF + so0, pb_);                                  \
            CPA16(base_ + BH_OFF + so1, pb_ + 8);                              \
            CPA16(base_ + BL_OFF + so0, pbl_);                                 \
            CPA16(base_ + BL_OFF + so1, pbl_ + 8);                             \
        }                                                                      \
        CP_COMMIT();                                                           \
    } while (0)

    ISSUE(0, 0);
    ISSUE(1, 1);

    int scur = 0;    // stage of chunk kt
    int snx2 = 2;    // stage for chunk kt+2
#pragma unroll 1
    for (int kt = 0; kt < NK; kt++) {
        if (kt == NK - 1) { CP_WAIT(0); } else { CP_WAIT(1); }
        __syncthreads();
        // stage snx2 was last read at iteration kt-1; the barrier above
        // ordered those reads -> safe to overwrite, no second barrier needed.
        if (kt + 2 < NK) ISSUE(kt + 2, snx2);

        uint32_t st = sb + (uint32_t)scur * STAGE;
#pragma unroll
        for (int k16 = 0; k16 < 2; k16++) {
            uint32_t ah[2][4], al2[2][4];
#pragma unroll
            for (int mt = 0; mt < 2; mt++) {
                uint32_t ad = st + aoff + mt * 1024 + ((((2 * k16 + ab)) ^ xa) << 4);
                LDSM_X4(ah[mt][0], ah[mt][1], ah[mt][2], ah[mt][3], ad);
                LDSM_X4(al2[mt][0], al2[mt][1], al2[mt][2], al2[mt][3], ad + 8192);
            }
#pragma unroll
            for (int np = 0; np < NP; np++) {
                uint32_t bh[4], bl2[4];
                uint32_t bd = st + BH_OFF + boff + np * 1024 + ((((2 * k16 + bb)) ^ xb) << 4);
                LDSM_X4(bh[0], bh[1], bh[2], bh[3], bd);
                LDSM_X4(bl2[0], bl2[1], bl2[2], bl2[3], bd + NTILE * 64);
#pragma unroll
                for (int mt = 0; mt < 2; mt++) {
#pragma unroll
                    for (int h = 0; h < 2; h++) {
                        int nt = np * 2 + h, h2 = h * 2;
                        float* C = acc[mt][nt];
                        MMA_BF16(C[0], C[1], C[2], C[3],
                                 ah[mt][0], ah[mt][1], ah[mt][2], ah[mt][3],
                                 bh[h2], bh[h2 + 1]);
                        MMA_BF16(C[0], C[1], C[2], C[3],
                                 al2[mt][0], al2[mt][1], al2[mt][2], al2[mt][3],
                                 bh[h2], bh[h2 + 1]);
                        MMA_BF16(C[0], C[1], C[2], C[3],
                                 ah[mt][0], ah[mt][1], ah[mt][2], ah[mt][3],
                                 bl2[h2], bl2[h2 + 1]);
                    }
                }
            }
        }
        scur = (scur == 2) ? 0 : scur + 1;
        snx2 = (snx2 == 2) ? 0 : snx2 + 1;
    }
#undef ISSUE

    // ---- epilogue ----
    int l4 = l >> 2, l2 = (l & 3) * 2;
#pragma unroll
    for (int mt = 0; mt < 2; mt++) {
#pragma unroll
        for (int nt = 0; nt < NT; nt++) {
            int row0 = by * 128 + wm * 32 + mt * 16 + l4;
            int col = bx * NTILE + wn * (NTILE / 2) + nt * 8 + l2;
            float2 v0 = make_float2(acc[mt][nt][0], acc[mt][nt][1]);
            float2 v1 = make_float2(acc[mt][nt][2], acc[mt][nt][3]);
            if (MODE == 0) {
                *(float2*)(g_sim + (size_t)row0 * N_TOK + col) = v0;
                *(float2*)(g_sim + (size_t)(row0 + 8) * N_TOK + col) = v1;
            } else {
                int o0 = (row0 & 1023) * 4 + (row0 >> 10);          // s*B + b
                int o1 = ((row0 + 8) & 1023) * 4 + ((row0 + 8) >> 10);
                *(float2*)(outp + (size_t)o0 * CDIM + col) = v0;
                *(float2*)(outp + (size_t)o1 * CDIM + col) = v1;
            }
        }
    }
}

// ---------------- block reductions (8 warps) ----------------
__device__ __forceinline__ float bred_sum(float v, float* wred, int t) {
#pragma unroll
    for (int o = 16; o > 0; o >>= 1) v += __shfl_xor_sync(0xffffffffu, v, o);
    __syncthreads();
    if ((t & 31) == 0) wred[t >> 5] = v;
    __syncthreads();
    float s = 0.f;
#pragma unroll
    for (int i = 0; i < 8; i++) s += wred[i];
    return s;
}
__device__ __forceinline__ float bred_max(float v, float* wred, int t) {
#pragma unroll
    for (int o = 16; o > 0; o >>= 1) v = fmaxf(v, __shfl_xor_sync(0xffffffffu, v, o));
    __syncthreads();
    if ((t & 31) == 0) wred[t >> 5] = v;
    __syncthreads();
    float s = -3.402823466e38f;
#pragma unroll
    for (int i = 0; i < 8; i++) s = fmaxf(s, wred[i]);
    return s;
}

// ---------------- softmax: token_norm + cut + softmax -> hi/lo bf16 probs ---
// Row kept entirely in registers (16 floats/thread); FFMA-poly exp (no MUFU).
__global__ __launch_bounds__(256) void k_softmax() {
    __shared__ float wred[8];
    int row = blockIdx.x, t = threadIdx.x;
    const float* Rp = g_sim + (size_t)row * N_TOK;

    float4 va[4];
    float s = 0.f;
#pragma unroll
    for (int u = 0; u < 4; u++) {
        va[u] = ((const float4*)Rp)[t + u * 256];
        s += (va[u].x + va[u].y) + (va[u].z + va[u].w);
    }
    float mean = fmaxf(bred_sum(s, wred, t) * (1.f / 4096.f), 0.f);

    float sub = mean * 1.2f;
    float mx = -3.402823466e38f;
#pragma unroll
    for (int u = 0; u < 4; u++) {
        va[u].x = (va[u].x - sub) * 3.0f; va[u].y = (va[u].y - sub) * 3.0f;
        va[u].z = (va[u].z - sub) * 3.0f; va[u].w = (va[u].w - sub) * 3.0f;
        mx = fmaxf(mx, fmaxf(fmaxf(va[u].x, va[u].y), fmaxf(va[u].z, va[u].w)));
    }
    float M = bred_max(mx, wred, t);

    float cut = fminf(M, 0.1f);
    const float invT = 1.f / 0.07f;
    float zs = 0.f;
#pragma unroll
    for (int u = 0; u < 4; u++) {
        va[u].x = (va[u].x < cut) ? 0.f : fexp((va[u].x - M) * invT);
        va[u].y = (va[u].y < cut) ? 0.f : fexp((va[u].y - M) * invT);
        va[u].z = (va[u].z < cut) ? 0.f : fexp((va[u].z - M) * invT);
        va[u].w = (va[u].w < cut) ? 0.f : fexp((va[u].w - M) * invT);
        zs += (va[u].x + va[u].y) + (va[u].z + va[u].w);
    }
    float inv = 1.f / bred_sum(zs, wred, t);

    __nv_bfloat16* Ph = g_ph + (size_t)row * N_TOK;
    __nv_bfloat16* Pl = g_pl + (size_t)row * N_TOK;
#pragma unroll
    for (int u = 0; u < 4; u++) {
        int c4 = t + u * 256;
        float x0 = va[u].x * inv, x1 = va[u].y * inv;
        float x2 = va[u].z * inv, x3 = va[u].w * inv;
        __nv_bfloat16 h0 = __float2bfloat16(x0);
        __nv_bfloat16 h1 = __float2bfloat16(x1);
        __nv_bfloat16 h2 = __float2bfloat16(x2);
        __nv_bfloat16 h3 = __float2bfloat16(x3);
        *(__nv_bfloat162*)(Ph + c4 * 4)     = __halves2bfloat162(h0, h1);
        *(__nv_bfloat162*)(Ph + c4 * 4 + 2) = __halves2bfloat162(h2, h3);
        __nv_bfloat16 l0 = __float2bfloat16(x0 - __bfloat162float(h0));
        __nv_bfloat16 l1 = __float2bfloat16(x1 - __bfloat162float(h1));
        __nv_bfloat16 l2b = __float2bfloat16(x2 - __bfloat162float(h2));
        __nv_bfloat16 l3 = __float2bfloat16(x3 - __bfloat162float(h3));
        *(__nv_bfloat162*)(Pl + c4 * 4)     = __halves2bfloat162(l0, l1);
        *(__nv_bfloat162*)(Pl + c4 * 4 + 2) = __halves2bfloat162(l2b, l3);
    }
}

// ---------------- launch ----------------
extern "C" void kernel_launch(void* const* d_in, const int* in_sizes, int n_in,
                              void* d_out, int out_size) {
    const float* ex = nullptr;
    const float* vext = nullptr;
    const int* idx = nullptr;
    for (int i = 0; i < n_in; i++) {
        if (in_sizes[i] == 4096) idx = (const int*)d_in[i];
        else if (in_sizes[i] == 2 * 2 * 1024 * 768) ex = (const float*)d_in[i];
        else if (in_sizes[i] == 48 * 24 * 24 * 64) vext = (const float*)d_in[i];
    }
    if (!ex || !vext || !idx) return;
    float* out = (float*)d_out;

    const int SMEM_G1 = 3 * 32768;                 // NTILE=128, 3 stages (96 KB)
    const int SMEM_G2 = 3 * (16384 + 2 * 96 * 64); // NTILE=96,  3 stages (84 KB)
    cudaFuncSetAttribute(k_gemm_mma<0, 128>, cudaFuncAttributeMaxDynamicSharedMemorySize, SMEM_G1);
    cudaFuncSetAttribute(k_gemm_mma<1, 96>, cudaFuncAttributeMaxDynamicSharedMemorySize, SMEM_G2);

    k_zero<<<96, 256>>>();
    k_resize<<<dim3(768, 16), 256>>>(vext);
    k_csum<<<dim3(16, 3), 256>>>(ex, idx);
    k_proxy<<<N_TOK, 256>>>(ex, idx);
    k_gemm_mma<0, 128><<<dim3(32, 32), 256, SMEM_G1>>>(out);
    k_softmax<<<N_TOK, 256>>>();
    k_gemm_mma<1, 96><<<dim3(8, 32), 256, SMEM_G2>>>(out);
}